// round 3
// baseline (speedup 1.0000x reference)
#include <cuda_runtime.h>
#include <cuda.h>
#include <cuda_fp16.h>
#include <cstdint>

// ---- arch gating: tcgen05 / cta_group::2 are only legal on arch-specific
// (sm_103a / sm_100a) targets. The harness build includes a plain compute_103
// PTX pass where ptxas rejects them, so compile the tcgen05 body only when the
// arch-feature macro is present. The runtime always uses the sm_103a cubin.
#if !defined(__CUDA_ARCH__) || defined(__CUDA_ARCH_FEAT_SM103_ALL) || \
    defined(__CUDA_ARCH_FEAT_SM100_ALL) || defined(__CUDA_ARCH_FEAT_SM101_ALL) || \
    (defined(__CUDA_ARCH_FAMILY_SPECIFIC__) && (__CUDA_ARCH_FAMILY_SPECIFIC__ >= 1000))
#define GB300_TCGEN05 1
#else
#define GB300_TCGEN05 0
#endif

// ======================= problem constants =======================
static constexpr int MM = 8192;
static constexpr int KK = 4096;
static constexpr int NN = 16384;
static constexpr int SCALE_KB = KK / 128;   // 32 scale blocks along K

// ======================= gemm tiling =======================
static constexpr int BK       = 64;             // k elems per stage (64 f16 = 128B = SW128 atom)
static constexpr int STAGES   = 4;
static constexpr int KCHUNKS  = KK / BK;        // 64
static constexpr int TILES_M  = MM / 256;       // 32 (256 m-rows per cg2 pair)
static constexpr int TILES_N  = NN / 512;       // 32 (512 n-cols per cg2 pair)
static constexpr int GRID     = TILES_M * TILES_N * 2;   // 2048 CTAs (1024 pairs)
static constexpr int GROUP_M  = 8;              // L2 supertile swizzle

// smem layout (dynamic)
static constexpr int SM_TMEM_PTR   = 0;
static constexpr int SM_FULL       = 16;        // 4 x 8B
static constexpr int SM_EMPTY      = 48;        // 4 x 8B
static constexpr int SM_DONE       = 80;        // 8B
static constexpr int A_STAGE_BYTES = 128 * 128;         // 128 rows x 128B
static constexpr int B_STAGE_BYTES = 2 * 128 * 128;     // two 128-row n-halves
static constexpr int SM_A          = 1024;
static constexpr int SM_B          = SM_A + STAGES * A_STAGE_BYTES;
static constexpr int SMEM_TOTAL    = SM_B + STAGES * B_STAGE_BYTES;   // 197632 B
static constexpr unsigned STAGE_TX = 6u * 128u * 128u;  // 98304 B (A+2B per CTA, x2 CTAs)

// idesc kind::f16, f16 inputs, fp32 acc, M=256 (cg2), N=256
static constexpr uint32_t IDESC_F16 =
    (1u << 4)            // dtype = F32
  | (0u << 7)            // atype = F16
  | (0u << 10)           // btype = F16
  | ((256u / 8) << 17)   // N
  | ((256u / 16) << 24); // M

// SW128 K-major smem descriptor base (LBO=1, SBO=64, version=1, layout=SW128)
static constexpr uint64_t SMEM_DESC_BASE_SW128 =
    (uint64_t(2) << 61) | (uint64_t(1) << 46) | (uint64_t(64) << 32) | (uint64_t(1) << 16);
#define MAKE_SMEM_DESC(base_addr) (SMEM_DESC_BASE_SW128 | ((uint64_t)((base_addr) >> 4) & 0x3FFF))

// ======================= device scratch (no cudaMalloc allowed) =======================
__device__ __align__(1024) __half g_x_h[(size_t)MM * KK];   // 64 MB
__device__ __align__(1024) __half g_w_h[(size_t)NN * KK];   // 128 MB

// ======================= PTX helpers =======================
__device__ __forceinline__ uint32_t smem_u32(const void* p) {
    uint32_t a;
    asm("{ .reg .u64 t; cvta.to.shared.u64 t, %1; cvt.u32.u64 %0, t; }" : "=r"(a) : "l"(p));
    return a;
}
__device__ __forceinline__ uint32_t ctarank() {
    uint32_t r; asm("mov.u32 %0, %%cluster_ctarank;" : "=r"(r)); return r;
}

#define MBAR_INIT(addr, cnt) \
    asm volatile("mbarrier.init.shared.b64 [%0], %1;" :: "r"(addr), "r"(cnt) : "memory")
#define MBAR_INVAL(addr) \
    asm volatile("mbarrier.inval.shared.b64 [%0];" :: "r"(addr) : "memory")
#define MBAR_EXPECT_TX(addr, bytes) \
    asm volatile("mbarrier.arrive.expect_tx.shared.b64 _, [%0], %1;" :: "r"(addr), "r"(bytes) : "memory")

#define MBAR_WAIT(addr, parity) do {                                                    \
    uint32_t _m = (uint32_t)(addr); uint32_t _p = (uint32_t)(parity); uint32_t _d;      \
    asm volatile("{\n\t.reg .pred p;\n\t"                                               \
        "mbarrier.try_wait.parity.acquire.cta.shared::cta.b64 p, [%1], %2;\n\t"         \
        "selp.b32 %0, 1, 0, p;\n\t}" : "=r"(_d) : "r"(_m), "r"(_p) : "memory");         \
    if (!_d) {                                                                          \
        asm volatile("{\n\t.reg .pred P1;\n\t"                                          \
            "WAIT_LOOP_%=:\n\t"                                                         \
            "mbarrier.try_wait.parity.acquire.cta.shared::cta.b64 P1, [%0], %1, 0x989680;\n\t" \
            "@P1 bra.uni WAIT_DONE_%=;\n\t"                                             \
            "bra.uni WAIT_LOOP_%=;\n\t"                                                 \
            "WAIT_DONE_%=:\n\t}" :: "r"(_m), "r"(_p) : "memory");                       \
    }                                                                                   \
} while (0)

#define MBAR_WAIT_RELAXED(addr, parity) do {                                            \
    uint32_t _m = (uint32_t)(addr); uint32_t _p = (uint32_t)(parity); uint32_t _d;      \
    asm volatile("{\n\t.reg .pred p;\n\t"                                               \
        "mbarrier.try_wait.parity.relaxed.cta.shared::cta.b64 p, [%1], %2, 0x989680;\n\t" \
        "selp.b32 %0, 1, 0, p;\n\t}" : "=r"(_d) : "r"(_m), "r"(_p) : "memory");         \
    if (!_d) {                                                                          \
        asm volatile("{\n\t.reg .pred P1;\n\t"                                          \
            "WAIT_LOOP_%=:\n\t"                                                         \
            "mbarrier.try_wait.parity.relaxed.cta.shared::cta.b64 P1, [%0], %1, 0x989680;\n\t" \
            "@P1 bra.uni WAIT_DONE_%=;\n\t"                                             \
            "bra.uni WAIT_LOOP_%=;\n\t"                                                 \
            "WAIT_DONE_%=:\n\t}" :: "r"(_m), "r"(_p) : "memory");                       \
    }                                                                                   \
} while (0)

#if GB300_TCGEN05
// cta_group::2 TMA load: both CTAs execute; complete_tx targets leader CTA's barrier
// (Sm100MmaPeerBitMask: clear bit 24 of the barrier address).
#define TMA_LOAD_3D_CG2(smem_addr, map_ptr, cx, cy, cz, mbar) \
    asm volatile("{\n\t.reg .b32 lb;\n\t"                                               \
        "and.b32 lb, %5, 0xFEFFFFFF;\n\t"                                               \
        "cp.async.bulk.tensor.3d.cta_group::2.shared::cluster.global"                   \
        ".tile.mbarrier::complete_tx::bytes [%0], [%1, {%2, %3, %4}], [lb];\n\t}"       \
        :: "r"((uint32_t)(smem_addr)), "l"(map_ptr),                                    \
           "r"((int32_t)(cx)), "r"((int32_t)(cy)), "r"((int32_t)(cz)),                  \
           "r"((uint32_t)(mbar)) : "memory")

#define TCGEN05_ALLOC_CG2(smem_res, ncols) \
    asm volatile("tcgen05.alloc.cta_group::2.sync.aligned.shared::cta.b32 [%0], %1;"    \
        :: "r"((uint32_t)(smem_res)), "r"((uint32_t)(ncols)) : "memory")
#define TCGEN05_DEALLOC_CG2(tmem, ncols) \
    asm volatile("tcgen05.dealloc.cta_group::2.sync.aligned.b32 %0, %1;" :: "r"(tmem), "r"(ncols))
#define TCGEN05_RELINQ_CG2() \
    asm volatile("tcgen05.relinquish_alloc_permit.cta_group::2.sync.aligned;")
#define TCGEN05_COMMIT_MC_CG2(mbar, mask) \
    asm volatile("tcgen05.commit.cta_group::2.mbarrier::arrive::one.shared::cluster.multicast::cluster.b64 [%0], %1;" \
        :: "r"((uint32_t)(mbar)), "h"((uint16_t)(mask)) : "memory")
#define TCGEN05_FENCE_AFTER() asm volatile("tcgen05.fence::after_thread_sync;" ::: "memory")
#define TCGEN05_WAIT_LD()     asm volatile("tcgen05.wait::ld.sync.aligned;" ::: "memory")

#define TCGEN05_LD_32X32B_X32(r, tmem_addr) \
    asm volatile("tcgen05.ld.sync.aligned.32x32b.x32.b32 "                              \
        "{%0, %1, %2, %3, %4, %5, %6, %7, "                                             \
        " %8, %9, %10, %11, %12, %13, %14, %15, "                                       \
        " %16, %17, %18, %19, %20, %21, %22, %23, "                                     \
        " %24, %25, %26, %27, %28, %29, %30, %31}, [%32];"                              \
        : "=r"((r)[0]),  "=r"((r)[1]),  "=r"((r)[2]),  "=r"((r)[3]),                    \
          "=r"((r)[4]),  "=r"((r)[5]),  "=r"((r)[6]),  "=r"((r)[7]),                    \
          "=r"((r)[8]),  "=r"((r)[9]),  "=r"((r)[10]), "=r"((r)[11]),                   \
          "=r"((r)[12]), "=r"((r)[13]), "=r"((r)[14]), "=r"((r)[15]),                   \
          "=r"((r)[16]), "=r"((r)[17]), "=r"((r)[18]), "=r"((r)[19]),                   \
          "=r"((r)[20]), "=r"((r)[21]), "=r"((r)[22]), "=r"((r)[23]),                   \
          "=r"((r)[24]), "=r"((r)[25]), "=r"((r)[26]), "=r"((r)[27]),                   \
          "=r"((r)[28]), "=r"((r)[29]), "=r"((r)[30]), "=r"((r)[31])                    \
        : "r"(tmem_addr))
#endif // GB300_TCGEN05

#define CLUSTER_SYNC() do {                                                             \
    asm volatile("barrier.cluster.arrive.aligned;" ::: "memory");                       \
    asm volatile("barrier.cluster.wait.aligned;" ::: "memory");                         \
} while (0)

// cg2 f16 SS MMA (M=256): 8-word disable-lane vector, all zero
__device__ __forceinline__ void mma_f16_ss_cg2(
    uint32_t d_tmem, uint64_t a_desc, uint64_t b_desc, uint32_t idesc, bool enable_d)
{
#if GB300_TCGEN05
    uint32_t en = enable_d ? 1u : 0u;
    asm volatile(
        "{\n\t.reg .pred p;\n\t"
        "setp.ne.u32 p, %5, 0;\n\t"
        "tcgen05.mma.cta_group::2.kind::f16 [%0], %1, %2, %3, "
        "{%4, %4, %4, %4, %4, %4, %4, %4}, p;\n\t}"
        :: "r"(d_tmem), "l"(a_desc), "l"(b_desc), "r"(idesc), "r"(0u), "r"(en)
        : "memory");
#endif
}

// ======================= kernel 1: x fp32 -> fp16 =======================
__global__ void cvt_x_kernel(const float* __restrict__ x, __half* __restrict__ xh, int n4)
{
    int i = blockIdx.x * blockDim.x + threadIdx.x;
    if (i >= n4) return;
    float4 v = reinterpret_cast<const float4*>(x)[i];
    union { __half2 h[2]; uint2 u; } cv;
    cv.h[0] = __floats2half2_rn(v.x, v.y);
    cv.h[1] = __floats2half2_rn(v.z, v.w);
    reinterpret_cast<uint2*>(xh)[i] = cv.u;
}

// ======================= kernel 2: w e4m3(fp32) * scale -> fp16 =======================
__global__ void dequant_w_kernel(const float* __restrict__ w, const float* __restrict__ sc,
                                 __half* __restrict__ wh, int n4)
{
    int i = blockIdx.x * blockDim.x + threadIdx.x;
    if (i >= n4) return;
    int n  = i >> 10;           // KK/4 = 1024 float4 per row
    int k4 = i & 1023;
    float s = __ldg(&sc[(n >> 7) * SCALE_KB + (k4 >> 5)]);
    float4 v = reinterpret_cast<const float4*>(w)[i];
    union { __half2 h[2]; uint2 u; } cv;
    cv.h[0] = __floats2half2_rn(v.x * s, v.y * s);
    cv.h[1] = __floats2half2_rn(v.z * s, v.w * s);
    reinterpret_cast<uint2*>(wh)[i] = cv.u;
}

// ======================= kernel 3: cg2 f16 tcgen05 GEMM =======================
// out[m,n] = sum_k xh[m,k] * wh[n,k] + bias[n]
__global__ void __launch_bounds__(192, 1)
gemm_f16_kernel(const __grid_constant__ CUtensorMap tma_a,
                const __grid_constant__ CUtensorMap tma_b,
                const float* __restrict__ bias,
                float* __restrict__ out)
{
#if GB300_TCGEN05
    extern __shared__ char smem[];
    const uint32_t sb  = smem_u32(smem);
    const int tid      = threadIdx.x;
    const int wid      = tid >> 5;
    const int lid      = tid & 31;
    const uint32_t rank = ctarank();

    // ---- tile mapping with GROUP_M supertile swizzle (L2 reuse) ----
    const int pair   = blockIdx.x >> 1;
    const int group  = pair / (GROUP_M * TILES_N);
    const int within = pair % (GROUP_M * TILES_N);
    const int pid_m  = group * GROUP_M + (within % GROUP_M);
    const int pid_n  = within / GROUP_M;
    const int m_base_cta = pid_m * 256 + (int)rank * 128;
    const int n_base     = pid_n * 512;

    // ---- init ----
    if (tid == 0) {
        #pragma unroll
        for (int s = 0; s < STAGES; s++) {
            MBAR_INIT(sb + SM_FULL  + s * 8, 1);
            MBAR_INIT(sb + SM_EMPTY + s * 8, 1);
        }
        MBAR_INIT(sb + SM_DONE, 1);
    }
    if (wid == 5) TCGEN05_ALLOC_CG2(sb + SM_TMEM_PTR, 512);
    __syncthreads();
    uint32_t tmem_base;
    asm volatile("ld.shared.b32 %0, [%1];" : "=r"(tmem_base) : "r"(sb + SM_TMEM_PTR));
    CLUSTER_SYNC();   // barriers + tmem visible cluster-wide before TMA/commit traffic

    // ---- producer: one thread per CTA issues cg2 TMA ----
    if (tid == 128) {
        for (int kc = 0; kc < KCHUNKS; ++kc) {
            const int s = kc & (STAGES - 1);
            const int r = kc >> 2;
            if (r > 0) MBAR_WAIT_RELAXED(sb + SM_EMPTY + s * 8, (r - 1) & 1);
            if (rank == 0) MBAR_EXPECT_TX(sb + SM_FULL + s * 8, STAGE_TX);
            const int kco = kc * BK;
            TMA_LOAD_3D_CG2(sb + SM_A + s * A_STAGE_BYTES, &tma_a,
                            kco, m_base_cta, 0, sb + SM_FULL + s * 8);
            TMA_LOAD_3D_CG2(sb + SM_B + s * B_STAGE_BYTES, &tma_b,
                            kco, n_base + (int)rank * 128, 0, sb + SM_FULL + s * 8);
            TMA_LOAD_3D_CG2(sb + SM_B + s * B_STAGE_BYTES + 16384, &tma_b,
                            kco, n_base + 256 + (int)rank * 128, 0, sb + SM_FULL + s * 8);
        }
    }

    // ---- MMA: single thread on leader CTA ----
    if (rank == 0 && tid == 160) {
        for (int kc = 0; kc < KCHUNKS; ++kc) {
            const int s = kc & (STAGES - 1);
            const int r = kc >> 2;
            MBAR_WAIT(sb + SM_FULL + s * 8, r & 1);
            const uint64_t ad = MAKE_SMEM_DESC(sb + SM_A + s * A_STAGE_BYTES);
            #pragma unroll
            for (int nh = 0; nh < 2; ++nh) {
                const uint64_t bd = MAKE_SMEM_DESC(sb + SM_B + s * B_STAGE_BYTES + nh * 16384);
                #pragma unroll
                for (int ks = 0; ks < 4; ++ks) {
                    // K=16 per dispatch; +2 desc units = +32B per k-step
                    mma_f16_ss_cg2(tmem_base + nh * 256,
                                   ad + ks * 2, bd + ks * 2,
                                   IDESC_F16, (kc > 0) || (ks > 0));
                }
            }
            TCGEN05_COMMIT_MC_CG2(sb + SM_EMPTY + s * 8, 0x3);
        }
        TCGEN05_COMMIT_MC_CG2(sb + SM_DONE, 0x3);
    }

    // ---- epilogue: warps 0-3 (128 threads) read TMEM, add bias, store ----
    if (wid < 4) {
        MBAR_WAIT(sb + SM_DONE, 0);
        TCGEN05_FENCE_AFTER();
        const int m = m_base_cta + wid * 32 + lid;
        float* orow = out + (size_t)m * NN + n_base;
        #pragma unroll 1
        for (int c = 0; c < 16; ++c) {
            uint32_t r[32];
            TCGEN05_LD_32X32B_X32(r, tmem_base + c * 32);
            TCGEN05_WAIT_LD();
            const int n0 = c * 32;
            #pragma unroll
            for (int q = 0; q < 8; ++q) {
                float4 bv = __ldg(reinterpret_cast<const float4*>(bias + n_base + n0 + q * 4));
                float4 o;
                o.x = __uint_as_float(r[q * 4 + 0]) + bv.x;
                o.y = __uint_as_float(r[q * 4 + 1]) + bv.y;
                o.z = __uint_as_float(r[q * 4 + 2]) + bv.z;
                o.w = __uint_as_float(r[q * 4 + 3]) + bv.w;
                reinterpret_cast<float4*>(orow + n0)[q] = o;
            }
        }
    }

    // ---- teardown ----
    __syncthreads();
    if (tid == 0) {
        #pragma unroll
        for (int s = 0; s < STAGES; s++) {
            MBAR_INVAL(sb + SM_FULL + s * 8);
            MBAR_INVAL(sb + SM_EMPTY + s * 8);
        }
        MBAR_INVAL(sb + SM_DONE);
    }
    __syncthreads();
    CLUSTER_SYNC();   // both CTAs done reading TMEM / peer SMEM
    if (wid == 5) {
        TCGEN05_RELINQ_CG2();
        TCGEN05_DEALLOC_CG2(tmem_base, 512);
    }
    CLUSTER_SYNC();
#endif // GB300_TCGEN05
}

// ======================= host =======================
typedef CUresult (*PFN_tmapEncode)(
    CUtensorMap*, CUtensorMapDataType, cuuint32_t, void*,
    const cuuint64_t*, const cuuint64_t*, const cuuint32_t*, const cuuint32_t*,
    CUtensorMapInterleave, CUtensorMapSwizzle, CUtensorMapL2promotion, CUtensorMapFloatOOBfill);

static void make_kmajor_map(PFN_tmapEncode enc, CUtensorMap* m, void* base,
                            cuuint64_t d0, cuuint64_t d1)
{
    cuuint64_t dims[3]    = {d0, d1, 1};
    cuuint64_t strides[2] = {d0 * 2, d0 * d1 * 2};
    cuuint32_t box[3]     = {64, 128, 1};     // 64 f16 = 128B inner (SW128 limit)
    cuuint32_t es[3]      = {1, 1, 1};
    enc(m, CU_TENSOR_MAP_DATA_TYPE_FLOAT16, 3, base, dims, strides, box, es,
        CU_TENSOR_MAP_INTERLEAVE_NONE, CU_TENSOR_MAP_SWIZZLE_128B,
        CU_TENSOR_MAP_L2_PROMOTION_L2_128B, CU_TENSOR_MAP_FLOAT_OOB_FILL_NONE);
}

extern "C" void kernel_launch(void* const* d_in, const int* in_sizes, int n_in,
                              void* d_out, int out_size)
{
    const float* x    = (const float*)d_in[0];
    const float* w    = (const float*)d_in[1];
    const float* sc   = (const float*)d_in[2];
    const float* bias = (const float*)d_in[3];
    float* out        = (float*)d_out;

    void *xh = nullptr, *wh = nullptr;
    cudaGetSymbolAddress(&xh, g_x_h);
    cudaGetSymbolAddress(&wh, g_w_h);

    {
        const int n4 = MM * KK / 4;
        cvt_x_kernel<<<(n4 + 255) / 256, 256>>>(x, (__half*)xh, n4);
    }
    {
        const int n4 = NN * KK / 4;
        dequant_w_kernel<<<(n4 + 255) / 256, 256>>>(w, sc, (__half*)wh, n4);
    }

    PFN_tmapEncode enc = nullptr;
    cudaDriverEntryPointQueryResult qr;
    cudaGetDriverEntryPoint("cuTensorMapEncodeTiled", (void**)&enc, cudaEnableDefault, &qr);
    if (!enc) return;

    CUtensorMap ta, tb;
    make_kmajor_map(enc, &ta, xh, (cuuint64_t)KK, (cuuint64_t)MM);
    make_kmajor_map(enc, &tb, wh, (cuuint64_t)KK, (cuuint64_t)NN);

    cudaFuncSetAttribute(gemm_f16_kernel,
                         cudaFuncAttributeMaxDynamicSharedMemorySize, SMEM_TOTAL);

    cudaLaunchConfig_t cfg = {};
    cfg.gridDim          = dim3(GRID, 1, 1);
    cfg.blockDim         = dim3(192, 1, 1);
    cfg.dynamicSmemBytes = SMEM_TOTAL;
    cfg.stream           = 0;
    cudaLaunchAttribute at[1];
    at[0].id = cudaLaunchAttributeClusterDimension;
    at[0].val.clusterDim.x = 2;
    at[0].val.clusterDim.y = 1;
    at[0].val.clusterDim.z = 1;
    cfg.attrs    = at;
    cfg.numAttrs = 1;
    cudaLaunchKernelEx(&cfg, gemm_f16_kernel, ta, tb, bias, out);
}

// round 5
// speedup vs baseline: 1.3396x; 1.3396x over previous
#include <cuda_runtime.h>
#include <cuda.h>
#include <cuda_fp16.h>
#include <cstdint>

// ---- arch gating: tcgen05 / cta_group::2 / TMA-multicast are only legal on
// arch-specific targets. The harness build includes a plain compute_103 PTX
// pass where ptxas rejects them, so compile the body only when the arch-feature
// macro is present. The runtime always uses the sm_103a cubin.
#if !defined(__CUDA_ARCH__) || defined(__CUDA_ARCH_FEAT_SM103_ALL) || \
    defined(__CUDA_ARCH_FEAT_SM100_ALL) || defined(__CUDA_ARCH_FEAT_SM101_ALL) || \
    (defined(__CUDA_ARCH_FAMILY_SPECIFIC__) && (__CUDA_ARCH_FAMILY_SPECIFIC__ >= 1000))
#define GB300_TCGEN05 1
#else
#define GB300_TCGEN05 0
#endif

// ======================= problem constants =======================
static constexpr int MM = 8192;
static constexpr int KK = 4096;
static constexpr int NN = 16384;
static constexpr int SCALE_KB = KK / 128;   // 32 scale blocks along K

// ======================= gemm tiling =======================
// 4-CTA cluster = 2 cg2 MMA pairs. Pair P = {rank 2P, 2P+1}. Both pairs share
// the SAME n-range (B multicast between {0,2} and {1,3}); pairs differ in M.
// Cluster tile: 512 M x 512 N.
static constexpr int BK        = 64;            // 64 f16 = 128B = SW128 atom
static constexpr int STAGES    = 4;
static constexpr int KCHUNKS   = KK / BK;       // 64
static constexpr int TILES_M2  = MM / 512;      // 16 (512 m-rows per cluster)
static constexpr int TILES_N   = NN / 512;      // 32
static constexpr int NCLUSTERS = TILES_M2 * TILES_N;   // 512
static constexpr int GRID      = NCLUSTERS * 4;        // 2048 CTAs
static constexpr int GROUP_M   = 8;             // L2 supertile swizzle (in 512-row units)

// smem layout (dynamic)
static constexpr int SM_TMEM_PTR   = 0;
static constexpr int SM_FULLA      = 16;        // 4 x 8B  (cg2 A completions, pair leader)
static constexpr int SM_FULLB      = 48;        // 4 x 8B  (B multicast, per-CTA + fwd)
static constexpr int SM_EMPTY      = 80;        // 4 x 8B  (2 arrivals: both pair commits)
static constexpr int SM_DONE       = 112;       // 8B
static constexpr int A_STAGE_BYTES = 128 * 128;         // 128 rows x 128B
static constexpr int B_STAGE_BYTES = 2 * 128 * 128;     // two 128-row n-halves
static constexpr int SM_A          = 1024;
static constexpr int SM_B          = SM_A + STAGES * A_STAGE_BYTES;
static constexpr int SMEM_TOTAL    = SM_B + STAGES * B_STAGE_BYTES;   // 197632 B
static constexpr unsigned A_TX     = 2u * 128u * 128u;  // 32768 B (pair A, 2 CTAs)
static constexpr unsigned B_TX     = 2u * 128u * 128u;  // 32768 B (2 n-halves per CTA)

// idesc kind::f16, f16 inputs, fp32 acc, M=256 (cg2), N=256
static constexpr uint32_t IDESC_F16 =
    (1u << 4) | (0u << 7) | (0u << 10) | ((256u / 8) << 17) | ((256u / 16) << 24);

// SW128 K-major smem descriptor base (LBO=1, SBO=64, version=1, layout=SW128)
static constexpr uint64_t SMEM_DESC_BASE_SW128 =
    (uint64_t(2) << 61) | (uint64_t(1) << 46) | (uint64_t(64) << 32) | (uint64_t(1) << 16);
#define MAKE_SMEM_DESC(base_addr) (SMEM_DESC_BASE_SW128 | ((uint64_t)((base_addr) >> 4) & 0x3FFF))

// ======================= device scratch (no cudaMalloc allowed) =======================
__device__ __align__(1024) __half g_x_h[(size_t)MM * KK];   // 64 MB
__device__ __align__(1024) __half g_w_h[(size_t)NN * KK];   // 128 MB

// ======================= PTX helpers =======================
__device__ __forceinline__ uint32_t smem_u32(const void* p) {
    uint32_t a;
    asm("{ .reg .u64 t; cvta.to.shared.u64 t, %1; cvt.u32.u64 %0, t; }" : "=r"(a) : "l"(p));
    return a;
}
__device__ __forceinline__ uint32_t ctarank() {
    uint32_t r; asm("mov.u32 %0, %%cluster_ctarank;" : "=r"(r)); return r;
}

#define MBAR_INIT(addr, cnt) \
    asm volatile("mbarrier.init.shared.b64 [%0], %1;" :: "r"(addr), "r"(cnt) : "memory")
#define MBAR_INVAL(addr) \
    asm volatile("mbarrier.inval.shared.b64 [%0];" :: "r"(addr) : "memory")
#define MBAR_EXPECT_TX(addr, bytes) \
    asm volatile("mbarrier.arrive.expect_tx.shared.b64 _, [%0], %1;" :: "r"(addr), "r"(bytes) : "memory")

#define MBAR_WAIT(addr, parity) do {                                                    \
    uint32_t _m = (uint32_t)(addr); uint32_t _p = (uint32_t)(parity); uint32_t _d;      \
    asm volatile("{\n\t.reg .pred p;\n\t"                                               \
        "mbarrier.try_wait.parity.acquire.cta.shared::cta.b64 p, [%1], %2;\n\t"         \
        "selp.b32 %0, 1, 0, p;\n\t}" : "=r"(_d) : "r"(_m), "r"(_p) : "memory");         \
    if (!_d) {                                                                          \
        asm volatile("{\n\t.reg .pred P1;\n\t"                                          \
            "WAIT_LOOP_%=:\n\t"                                                         \
            "mbarrier.try_wait.parity.acquire.cta.shared::cta.b64 P1, [%0], %1, 0x989680;\n\t" \
            "@P1 bra.uni WAIT_DONE_%=;\n\t"                                             \
            "bra.uni WAIT_LOOP_%=;\n\t"                                                 \
            "WAIT_DONE_%=:\n\t}" :: "r"(_m), "r"(_p) : "memory");                       \
    }                                                                                   \
} while (0)

#define MBAR_WAIT_RELAXED(addr, parity) do {                                            \
    uint32_t _m = (uint32_t)(addr); uint32_t _p = (uint32_t)(parity); uint32_t _d;      \
    asm volatile("{\n\t.reg .pred p;\n\t"                                               \
        "mbarrier.try_wait.parity.relaxed.cta.shared::cta.b64 p, [%1], %2, 0x989680;\n\t" \
        "selp.b32 %0, 1, 0, p;\n\t}" : "=r"(_d) : "r"(_m), "r"(_p) : "memory");         \
    if (!_d) {                                                                          \
        asm volatile("{\n\t.reg .pred P1;\n\t"                                          \
            "WAIT_LOOP_%=:\n\t"                                                         \
            "mbarrier.try_wait.parity.relaxed.cta.shared::cta.b64 P1, [%0], %1, 0x989680;\n\t" \
            "@P1 bra.uni WAIT_DONE_%=;\n\t"                                             \
            "bra.uni WAIT_LOOP_%=;\n\t"                                                 \
            "WAIT_DONE_%=:\n\t}" :: "r"(_m), "r"(_p) : "memory");                       \
    }                                                                                   \
} while (0)

#if GB300_TCGEN05
// cta_group::2 TMA load: both pair CTAs execute; complete_tx targets the pair
// leader's barrier (clear bit 24 = rank LSB of the DSMEM address).
#define TMA_LOAD_3D_CG2(smem_addr, map_ptr, cx, cy, cz, mbar) \
    asm volatile("{\n\t.reg .b32 lb;\n\t"                                               \
        "and.b32 lb, %5, 0xFEFFFFFF;\n\t"                                               \
        "cp.async.bulk.tensor.3d.cta_group::2.shared::cluster.global"                   \
        ".tile.mbarrier::complete_tx::bytes [%0], [%1, {%2, %3, %4}], [lb];\n\t}"       \
        :: "r"((uint32_t)(smem_addr)), "l"(map_ptr),                                    \
           "r"((int32_t)(cx)), "r"((int32_t)(cy)), "r"((int32_t)(cz)),                  \
           "r"((uint32_t)(mbar)) : "memory")

// Multicast TMA load: delivers data + complete_tx to the same SMEM offset in
// every CTA whose bit is set in cta_mask (each receiver's OWN barrier).
#define TMA_LOAD_3D_MC(smem_addr, map_ptr, cx, cy, cz, mbar, cta_mask) \
    asm volatile("cp.async.bulk.tensor.3d.shared::cluster.global"                       \
        ".tile.mbarrier::complete_tx::bytes.multicast::cluster "                        \
        "[%0], [%1, {%2, %3, %4}], [%5], %6;"                                           \
        :: "r"((uint32_t)(smem_addr)), "l"(map_ptr),                                    \
           "r"((int32_t)(cx)), "r"((int32_t)(cy)), "r"((int32_t)(cz)),                  \
           "r"((uint32_t)(mbar)), "h"((uint16_t)(cta_mask)) : "memory")

// Arrive on the mbarrier at the same SMEM offset in cluster CTA target_rank.
#define MBAR_ARRIVE_REMOTE(local_addr, target_rank) \
    asm volatile("{\n\t.reg .b32 ra;\n\t"                                               \
        "mapa.shared::cluster.u32 ra, %0, %1;\n\t"                                      \
        "mbarrier.arrive.shared::cluster.b64 _, [ra];\n\t}"                             \
        :: "r"((uint32_t)(local_addr)), "r"((uint32_t)(target_rank)) : "memory")

#define TCGEN05_ALLOC_CG2(smem_res, ncols) \
    asm volatile("tcgen05.alloc.cta_group::2.sync.aligned.shared::cta.b32 [%0], %1;"    \
        :: "r"((uint32_t)(smem_res)), "r"((uint32_t)(ncols)) : "memory")
#define TCGEN05_DEALLOC_CG2(tmem, ncols) \
    asm volatile("tcgen05.dealloc.cta_group::2.sync.aligned.b32 %0, %1;" :: "r"(tmem), "r"(ncols))
#define TCGEN05_RELINQ_CG2() \
    asm volatile("tcgen05.relinquish_alloc_permit.cta_group::2.sync.aligned;")
#define TCGEN05_COMMIT_MC_CG2(mbar, mask) \
    asm volatile("tcgen05.commit.cta_group::2.mbarrier::arrive::one.shared::cluster.multicast::cluster.b64 [%0], %1;" \
        :: "r"((uint32_t)(mbar)), "h"((uint16_t)(mask)) : "memory")
#define TCGEN05_FENCE_AFTER() asm volatile("tcgen05.fence::after_thread_sync;" ::: "memory")
#define TCGEN05_WAIT_LD()     asm volatile("tcgen05.wait::ld.sync.aligned;" ::: "memory")

#define TCGEN05_LD_32X32B_X32(r, tmem_addr) \
    asm volatile("tcgen05.ld.sync.aligned.32x32b.x32.b32 "                              \
        "{%0, %1, %2, %3, %4, %5, %6, %7, "                                             \
        " %8, %9, %10, %11, %12, %13, %14, %15, "                                       \
        " %16, %17, %18, %19, %20, %21, %22, %23, "                                     \
        " %24, %25, %26, %27, %28, %29, %30, %31}, [%32];"                              \
        : "=r"((r)[0]),  "=r"((r)[1]),  "=r"((r)[2]),  "=r"((r)[3]),                    \
          "=r"((r)[4]),  "=r"((r)[5]),  "=r"((r)[6]),  "=r"((r)[7]),                    \
          "=r"((r)[8]),  "=r"((r)[9]),  "=r"((r)[10]), "=r"((r)[11]),                   \
          "=r"((r)[12]), "=r"((r)[13]), "=r"((r)[14]), "=r"((r)[15]),                   \
          "=r"((r)[16]), "=r"((r)[17]), "=r"((r)[18]), "=r"((r)[19]),                   \
          "=r"((r)[20]), "=r"((r)[21]), "=r"((r)[22]), "=r"((r)[23]),                   \
          "=r"((r)[24]), "=r"((r)[25]), "=r"((r)[26]), "=r"((r)[27]),                   \
          "=r"((r)[28]), "=r"((r)[29]), "=r"((r)[30]), "=r"((r)[31])                    \
        : "r"(tmem_addr))
#endif // GB300_TCGEN05

#define CLUSTER_SYNC() do {                                                             \
    asm volatile("barrier.cluster.arrive.aligned;" ::: "memory");                       \
    asm volatile("barrier.cluster.wait.aligned;" ::: "memory");                         \
} while (0)

// cg2 f16 SS MMA (M=256): 8-word disable-lane vector, all zero
__device__ __forceinline__ void mma_f16_ss_cg2(
    uint32_t d_tmem, uint64_t a_desc, uint64_t b_desc, uint32_t idesc, bool enable_d)
{
#if GB300_TCGEN05
    uint32_t en = enable_d ? 1u : 0u;
    asm volatile(
        "{\n\t.reg .pred p;\n\t"
        "setp.ne.u32 p, %5, 0;\n\t"
        "tcgen05.mma.cta_group::2.kind::f16 [%0], %1, %2, %3, "
        "{%4, %4, %4, %4, %4, %4, %4, %4}, p;\n\t}"
        :: "r"(d_tmem), "l"(a_desc), "l"(b_desc), "r"(idesc), "r"(0u), "r"(en)
        : "memory");
#endif
}

// ======================= kernel 1: fused prep (x cvt + w dequant) =======================
// One kernel so the per-call launch sequence is (prep, gemm) and ncu -s 5
// lands on the GEMM. Blocks [0, XB) convert x; blocks [XB, XB+WB) dequant w.
static constexpr int XB = (MM * KK / 4) / 256;   // 32768
static constexpr int WB = (NN * KK / 4) / 256;   // 65536

__global__ void __launch_bounds__(256) prep_kernel(
    const float* __restrict__ x, const float* __restrict__ w,
    const float* __restrict__ sc,
    __half* __restrict__ xh, __half* __restrict__ wh)
{
    int b = blockIdx.x;
    if (b < XB) {
        int i = b * 256 + threadIdx.x;
        float4 v = reinterpret_cast<const float4*>(x)[i];
        union { __half2 h[2]; uint2 u; } cv;
        cv.h[0] = __floats2half2_rn(v.x, v.y);
        cv.h[1] = __floats2half2_rn(v.z, v.w);
        reinterpret_cast<uint2*>(xh)[i] = cv.u;
    } else {
        int i = (b - XB) * 256 + threadIdx.x;
        int n  = i >> 10;           // KK/4 = 1024 float4 per row
        int k4 = i & 1023;
        float s = __ldg(&sc[(n >> 7) * SCALE_KB + (k4 >> 5)]);
        float4 v = reinterpret_cast<const float4*>(w)[i];
        union { __half2 h[2]; uint2 u; } cv;
        cv.h[0] = __floats2half2_rn(v.x * s, v.y * s);
        cv.h[1] = __floats2half2_rn(v.z * s, v.w * s);
        reinterpret_cast<uint2*>(wh)[i] = cv.u;
    }
}

// ======================= kernel 2: cluster-4, 2x cg2 pairs, B-multicast GEMM ============
// out[m,n] = sum_k xh[m,k] * wh[n,k] + bias[n]
__global__ void __launch_bounds__(192, 1)
gemm_f16_kernel(const __grid_constant__ CUtensorMap tma_a,
                const __grid_constant__ CUtensorMap tma_b,
                const float* __restrict__ bias,
                float* __restrict__ out)
{
#if GB300_TCGEN05
    extern __shared__ char smem[];
    const uint32_t sb  = smem_u32(smem);
    const int tid      = threadIdx.x;
    const int wid      = tid >> 5;
    const int lid      = tid & 31;
    const uint32_t rank = ctarank();          // 0..3
    const int P  = (int)(rank >> 1);          // pair id within cluster
    const int rp = (int)(rank & 1);           // rank within pair

    // ---- tile mapping: cluster covers 512M x 512N; GROUP_M supertile swizzle ----
    const int c      = blockIdx.x >> 2;
    const int group  = c / (GROUP_M * TILES_N);
    const int within = c % (GROUP_M * TILES_N);
    const int pm2    = group * GROUP_M + (within % GROUP_M);   // [0, 16)
    const int pn     = within / GROUP_M;                       // [0, 32)
    const int m_base_cta = pm2 * 512 + P * 256 + rp * 128;
    const int n_base     = pn * 512;

    // ---- init ----
    if (tid == 0) {
        #pragma unroll
        for (int s = 0; s < STAGES; s++) {
            MBAR_INIT(sb + SM_FULLA + s * 8, 1);
            // leader (even rank): own expect_tx + follower forward-arrive = 2
            MBAR_INIT(sb + SM_FULLB + s * 8, rp ? 1 : 2);
            // two pair-leader commits per round
            MBAR_INIT(sb + SM_EMPTY + s * 8, 2);
        }
        MBAR_INIT(sb + SM_DONE, 1);
    }
    if (wid == 5) TCGEN05_ALLOC_CG2(sb + SM_TMEM_PTR, 512);
    __syncthreads();
    uint32_t tmem_base;
    asm volatile("ld.shared.b32 %0, [%1];" : "=r"(tmem_base) : "r"(sb + SM_TMEM_PTR));
    CLUSTER_SYNC();   // barriers + tmem visible cluster-wide before TMA/commit traffic

    // ---- producer: one thread per CTA ----
    if (tid == 128) {
        const uint16_t bmask = rank == 0 ? 0x5 : 0xA;   // {0,2} or {1,3}
        for (int kc = 0; kc < KCHUNKS; ++kc) {
            const int s = kc & (STAGES - 1);
            const int r = kc >> 2;
            if (r > 0) MBAR_WAIT_RELAXED(sb + SM_EMPTY + s * 8, (r - 1) & 1);
            const int kco = kc * BK;
            // A: cg2 load (both pair CTAs), completes on pair leader's fullA
            if (rp == 0) MBAR_EXPECT_TX(sb + SM_FULLA + s * 8, A_TX);
            TMA_LOAD_3D_CG2(sb + SM_A + s * A_STAGE_BYTES, &tma_a,
                            kco, m_base_cta, 0, sb + SM_FULLA + s * 8);
            // B: every CTA expects its own B bytes; only ranks 0/1 issue (multicast)
            MBAR_EXPECT_TX(sb + SM_FULLB + s * 8, B_TX);
            if (rank < 2) {
                TMA_LOAD_3D_MC(sb + SM_B + s * B_STAGE_BYTES, &tma_b,
                               kco, n_base + rp * 128, 0,
                               sb + SM_FULLB + s * 8, bmask);
                TMA_LOAD_3D_MC(sb + SM_B + s * B_STAGE_BYTES + 16384, &tma_b,
                               kco, n_base + 256 + rp * 128, 0,
                               sb + SM_FULLB + s * 8, bmask);
            }
        }
    }

    // ---- tid 160: MMA issuer (even ranks) / B-forwarder (odd ranks) ----
    if (tid == 160) {
        if (rp == 0) {
            // pair leader: wait A + B (own fullB fires after own tx + follower fwd)
            for (int kc = 0; kc < KCHUNKS; ++kc) {
                const int s = kc & (STAGES - 1);
                const int r = kc >> 2;
                MBAR_WAIT(sb + SM_FULLA + s * 8, r & 1);
                MBAR_WAIT(sb + SM_FULLB + s * 8, r & 1);
                const uint64_t ad = MAKE_SMEM_DESC(sb + SM_A + s * A_STAGE_BYTES);
                #pragma unroll
                for (int nh = 0; nh < 2; ++nh) {
                    const uint64_t bd = MAKE_SMEM_DESC(sb + SM_B + s * B_STAGE_BYTES + nh * 16384);
                    #pragma unroll
                    for (int ks = 0; ks < 4; ++ks) {
                        mma_f16_ss_cg2(tmem_base + nh * 256,
                                       ad + ks * 2, bd + ks * 2,
                                       IDESC_F16, (kc > 0) || (ks > 0));
                    }
                }
                TCGEN05_COMMIT_MC_CG2(sb + SM_EMPTY + s * 8, 0xF);
            }
            TCGEN05_COMMIT_MC_CG2(sb + SM_DONE, rank == 0 ? 0x3 : 0xC);
        } else {
            // follower: forward own B arrival to pair leader's fullB
            const uint32_t leader = rank - 1;
            for (int kc = 0; kc < KCHUNKS; ++kc) {
                const int s = kc & (STAGES - 1);
                const int r = kc >> 2;
                MBAR_WAIT(sb + SM_FULLB + s * 8, r & 1);
                MBAR_ARRIVE_REMOTE(sb + SM_FULLB + s * 8, leader);
            }
        }
    }

    // ---- epilogue: warps 0-3 read TMEM, add bias, store ----
    if (wid < 4) {
        MBAR_WAIT(sb + SM_DONE, 0);
        TCGEN05_FENCE_AFTER();
        const int m = m_base_cta + wid * 32 + lid;
        float* orow = out + (size_t)m * NN + n_base;
        #pragma unroll 1
        for (int cc = 0; cc < 16; ++cc) {
            uint32_t r[32];
            TCGEN05_LD_32X32B_X32(r, tmem_base + cc * 32);
            TCGEN05_WAIT_LD();
            const int n0 = cc * 32;
            #pragma unroll
            for (int q = 0; q < 8; ++q) {
                float4 bv = __ldg(reinterpret_cast<const float4*>(bias + n_base + n0 + q * 4));
                float4 o;
                o.x = __uint_as_float(r[q * 4 + 0]) + bv.x;
                o.y = __uint_as_float(r[q * 4 + 1]) + bv.y;
                o.z = __uint_as_float(r[q * 4 + 2]) + bv.z;
                o.w = __uint_as_float(r[q * 4 + 3]) + bv.w;
                reinterpret_cast<float4*>(orow + n0)[q] = o;
            }
        }
    }

    // ---- teardown ----
    __syncthreads();
    if (tid == 0) {
        #pragma unroll
        for (int s = 0; s < STAGES; s++) {
            MBAR_INVAL(sb + SM_FULLA + s * 8);
            MBAR_INVAL(sb + SM_FULLB + s * 8);
            MBAR_INVAL(sb + SM_EMPTY + s * 8);
        }
        MBAR_INVAL(sb + SM_DONE);
    }
    __syncthreads();
    CLUSTER_SYNC();   // everyone done reading peer SMEM / TMEM
    if (wid == 5) {
        TCGEN05_RELINQ_CG2();
        TCGEN05_DEALLOC_CG2(tmem_base, 512);
    }
    CLUSTER_SYNC();
#endif // GB300_TCGEN05
}

// ======================= host =======================
typedef CUresult (*PFN_tmapEncode)(
    CUtensorMap*, CUtensorMapDataType, cuuint32_t, void*,
    const cuuint64_t*, const cuuint64_t*, const cuuint32_t*, const cuuint32_t*,
    CUtensorMapInterleave, CUtensorMapSwizzle, CUtensorMapL2promotion, CUtensorMapFloatOOBfill);

static void make_kmajor_map(PFN_tmapEncode enc, CUtensorMap* m, void* base,
                            cuuint64_t d0, cuuint64_t d1)
{
    cuuint64_t dims[3]    = {d0, d1, 1};
    cuuint64_t strides[2] = {d0 * 2, d0 * d1 * 2};
    cuuint32_t box[3]     = {64, 128, 1};     // 64 f16 = 128B inner (SW128 limit)
    cuuint32_t es[3]      = {1, 1, 1};
    enc(m, CU_TENSOR_MAP_DATA_TYPE_FLOAT16, 3, base, dims, strides, box, es,
        CU_TENSOR_MAP_INTERLEAVE_NONE, CU_TENSOR_MAP_SWIZZLE_128B,
        CU_TENSOR_MAP_L2_PROMOTION_L2_128B, CU_TENSOR_MAP_FLOAT_OOB_FILL_NONE);
}

extern "C" void kernel_launch(void* const* d_in, const int* in_sizes, int n_in,
                              void* d_out, int out_size)
{
    const float* x    = (const float*)d_in[0];
    const float* w    = (const float*)d_in[1];
    const float* sc   = (const float*)d_in[2];
    const float* bias = (const float*)d_in[3];
    float* out        = (float*)d_out;

    void *xh = nullptr, *wh = nullptr;
    cudaGetSymbolAddress(&xh, g_x_h);
    cudaGetSymbolAddress(&wh, g_w_h);

    prep_kernel<<<XB + WB, 256>>>(x, w, sc, (__half*)xh, (__half*)wh);

    PFN_tmapEncode enc = nullptr;
    cudaDriverEntryPointQueryResult qr;
    cudaGetDriverEntryPoint("cuTensorMapEncodeTiled", (void**)&enc, cudaEnableDefault, &qr);
    if (!enc) return;

    CUtensorMap ta, tb;
    make_kmajor_map(enc, &ta, xh, (cuuint64_t)KK, (cuuint64_t)MM);
    make_kmajor_map(enc, &tb, wh, (cuuint64_t)KK, (cuuint64_t)NN);

    cudaFuncSetAttribute(gemm_f16_kernel,
                         cudaFuncAttributeMaxDynamicSharedMemorySize, SMEM_TOTAL);

    cudaLaunchConfig_t cfg = {};
    cfg.gridDim          = dim3(GRID, 1, 1);
    cfg.blockDim         = dim3(192, 1, 1);
    cfg.dynamicSmemBytes = SMEM_TOTAL;
    cfg.stream           = 0;
    cudaLaunchAttribute at[1];
    at[0].id = cudaLaunchAttributeClusterDimension;
    at[0].val.clusterDim.x = 4;
    at[0].val.clusterDim.y = 1;
    at[0].val.clusterDim.z = 1;
    cfg.attrs    = at;
    cfg.numAttrs = 1;
    cudaLaunchKernelEx(&cfg, gemm_f16_kernel, ta, tb, bias, out);
}